// round 16
// baseline (speedup 1.0000x reference)
#include <cuda_runtime.h>
#include <cuda_bf16.h>
#include <cstdint>
#include <cmath>

// ---------------------------------------------------------------------------
// Problem constants: B=8, L=2048, D=1024 (H=16, E=64 -> C = 1024), topk=22
// ---------------------------------------------------------------------------
#define BATCH 8
#define SEQ   2048
#define DIM   1024
#define TOPK  22
#define ELEMS (BATCH * SEQ * DIM)   // 16777216

// Scratch (allocation-free: __device__ globals)
__device__ float g_Qt[ELEMS];     // Q projected+transposed [B,C,L]
__device__ float g_Kt[ELEMS];     // K projected+transposed [B,C,L]
__device__ float g_corr[ELEMS];   // corr [B,C,L]
__device__ float g_Vs[BATCH * 8 * DIM];  // V rows l=0..7 only
__device__ float g_Rs[BATCH * 8 * DIM];  // aggregated result (periodic rows)
__device__ float g_To[BATCH * 8 * DIM];  // Rs @ Wo + bo
__device__ __nv_bfloat16 g_Xhi[ELEMS];   // split-bf16 staging for activations
__device__ __nv_bfloat16 g_Xlo[ELEMS];
__device__ __nv_bfloat16 g_Whi[DIM * DIM];
__device__ __nv_bfloat16 g_Wlo[DIM * DIM];
__device__ float2 g_tw[1024];            // FFT twiddles exp(+i 2 pi e / 2048)

// ---------------------------------------------------------------------------
// Split fp32 -> (hi, lo) bf16 pair.  x ~= hi + lo with ~17-bit mantissa.
// ---------------------------------------------------------------------------
__global__ void split_bf16(const float* __restrict__ x,
                           __nv_bfloat16* __restrict__ hi,
                           __nv_bfloat16* __restrict__ lo)
{
    const int i = blockIdx.x * 256 + threadIdx.x;  // one float4 per thread
    float4 v = ((const float4*)x)[i];
    float vv[4] = {v.x, v.y, v.z, v.w};
    __nv_bfloat16 h[4], l[4];
#pragma unroll
    for (int j = 0; j < 4; j++) {
        h[j] = __float2bfloat16(vv[j]);
        l[j] = __float2bfloat16(vv[j] - __bfloat162float(h[j]));
    }
    *(uint2*)(hi + 4 * (size_t)i) = *(uint2*)h;
    *(uint2*)(lo + 4 * (size_t)i) = *(uint2*)l;
}

// ---------------------------------------------------------------------------
// Tensor-core GEMM with fused transposed output:
//   T[b, n, l] = (X @ W + bias)[b*2048 + l, n]
// 3-stage cp.async pipeline, k-step 32, 8 warps (2x4), tile 128x128,
// bf16 hi/lo split (3 mma products).   [proven R10 version]
// ---------------------------------------------------------------------------
#define APAD 40    // A smem row halves (32 data + 8 pad)
#define BPAD 136   // B smem row halves (128 data + 8 pad)
#define A_BYTES (128 * APAD * 2)          // 10240
#define B_BYTES (32 * BPAD * 2)           // 8704
#define STAGE_BYTES (2 * A_BYTES + 2 * B_BYTES)  // 37888
#define GEMM_DSMEM (3 * STAGE_BYTES)             // 113664

__device__ __forceinline__ void cp16(uint32_t d, const void* s) {
    asm volatile("cp.async.cg.shared.global [%0], [%1], 16;\n" :: "r"(d), "l"(s));
}
__device__ __forceinline__ void cp_commit() { asm volatile("cp.async.commit_group;\n"); }
__device__ __forceinline__ void cp_wait0()  { asm volatile("cp.async.wait_group 0;\n"); }
__device__ __forceinline__ void cp_wait1()  { asm volatile("cp.async.wait_group 1;\n"); }

__device__ __forceinline__ void ldsm4(uint32_t* r, uint32_t a) {
    asm volatile("ldmatrix.sync.aligned.m8n8.x4.shared.b16 {%0,%1,%2,%3},[%4];"
                 : "=r"(r[0]), "=r"(r[1]), "=r"(r[2]), "=r"(r[3]) : "r"(a));
}
__device__ __forceinline__ void ldsm4t(uint32_t* r, uint32_t a) {
    asm volatile("ldmatrix.sync.aligned.m8n8.x4.trans.shared.b16 {%0,%1,%2,%3},[%4];"
                 : "=r"(r[0]), "=r"(r[1]), "=r"(r[2]), "=r"(r[3]) : "r"(a));
}
__device__ __forceinline__ void mma_bf16(float* c, const uint32_t* a, const uint32_t* b) {
    asm volatile("mma.sync.aligned.m16n8k16.row.col.f32.bf16.bf16.f32 "
                 "{%0,%1,%2,%3},{%4,%5,%6,%7},{%8,%9},{%0,%1,%2,%3};"
                 : "+f"(c[0]), "+f"(c[1]), "+f"(c[2]), "+f"(c[3])
                 : "r"(a[0]), "r"(a[1]), "r"(a[2]), "r"(a[3]), "r"(b[0]), "r"(b[1]));
}

__global__ __launch_bounds__(256) void gemm_bf16x2_t(
    const __nv_bfloat16* __restrict__ Ahi, const __nv_bfloat16* __restrict__ Alo,
    const __nv_bfloat16* __restrict__ Bhi, const __nv_bfloat16* __restrict__ Blo,
    const float* __restrict__ bias, float* __restrict__ T)
{
    extern __shared__ __align__(16) char dsm[];

    const int tid = threadIdx.x;
    const int warp = tid >> 5, lane = tid & 31;
    const int wm = warp >> 2, wn = warp & 3;          // 2 x 4 warp grid
    const int m0 = blockIdx.y * 128, n0 = blockIdx.x * 128;

    float acc[4][4][4];
#pragma unroll
    for (int i = 0; i < 4; i++)
#pragma unroll
        for (int j = 0; j < 4; j++)
#pragma unroll
            for (int k = 0; k < 4; k++) acc[i][j][k] = 0.0f;

#define SAH(s) ((__nv_bfloat16*)(dsm + (s) * STAGE_BYTES))
#define SAL(s) ((__nv_bfloat16*)(dsm + (s) * STAGE_BYTES + A_BYTES))
#define SBH(s) ((__nv_bfloat16*)(dsm + (s) * STAGE_BYTES + 2 * A_BYTES))
#define SBL(s) ((__nv_bfloat16*)(dsm + (s) * STAGE_BYTES + 2 * A_BYTES + B_BYTES))

#define GEMM_ISSUE(s, k0)                                                              \
    do {                                                                               \
        _Pragma("unroll")                                                              \
        for (int t = 0; t < 2; t++) {                                                  \
            const int id = tid + t * 256;                                              \
            const int arow = id >> 2, ac4 = id & 3;                                    \
            cp16((uint32_t)__cvta_generic_to_shared(SAH(s) + arow * APAD + ac4 * 8),   \
                 Ahi + (size_t)(m0 + arow) * 1024 + (k0) + ac4 * 8);                   \
            cp16((uint32_t)__cvta_generic_to_shared(SAL(s) + arow * APAD + ac4 * 8),   \
                 Alo + (size_t)(m0 + arow) * 1024 + (k0) + ac4 * 8);                   \
            const int brow = id >> 4, bc = id & 15;                                    \
            cp16((uint32_t)__cvta_generic_to_shared(SBH(s) + brow * BPAD + bc * 8),    \
                 Bhi + (size_t)((k0) + brow) * 1024 + n0 + bc * 8);                    \
            cp16((uint32_t)__cvta_generic_to_shared(SBL(s) + brow * BPAD + bc * 8),    \
                 Blo + (size_t)((k0) + brow) * 1024 + n0 + bc * 8);                    \
        }                                                                              \
        cp_commit();                                                                   \
    } while (0)

    GEMM_ISSUE(0, 0);
    GEMM_ISSUE(1, 32);

    const int ar = lane & 15, ac8 = (lane >> 4) * 8;    // ldmatrix lane addressing

    for (int it = 0; it < 32; it++) {
        if (it == 31) cp_wait0(); else cp_wait1();
        __syncthreads();

        const int s = it % 3;
#pragma unroll
        for (int kk = 0; kk < 32; kk += 16) {
            uint32_t ah[4][4], al[4][4], bh[4][2], bl[4][2];
#pragma unroll
            for (int mb = 0; mb < 4; mb++) {
                const int row = wm * 64 + mb * 16 + ar;
                ldsm4(ah[mb], (uint32_t)__cvta_generic_to_shared(SAH(s) + row * APAD + kk + ac8));
                ldsm4(al[mb], (uint32_t)__cvta_generic_to_shared(SAL(s) + row * APAD + kk + ac8));
            }
#pragma unroll
            for (int nb2 = 0; nb2 < 2; nb2++) {
                uint32_t r[4];
                const int col = wn * 32 + nb2 * 16 + ac8;
                ldsm4t(r, (uint32_t)__cvta_generic_to_shared(SBH(s) + (kk + ar) * BPAD + col));
                bh[nb2 * 2][0] = r[0]; bh[nb2 * 2][1] = r[1];
                bh[nb2 * 2 + 1][0] = r[2]; bh[nb2 * 2 + 1][1] = r[3];
                ldsm4t(r, (uint32_t)__cvta_generic_to_shared(SBL(s) + (kk + ar) * BPAD + col));
                bl[nb2 * 2][0] = r[0]; bl[nb2 * 2][1] = r[1];
                bl[nb2 * 2 + 1][0] = r[2]; bl[nb2 * 2 + 1][1] = r[3];
            }
#pragma unroll
            for (int mb = 0; mb < 4; mb++)
#pragma unroll
                for (int nb = 0; nb < 4; nb++)
                    mma_bf16(acc[mb][nb], ah[mb], bh[nb]);   // hi*hi
#pragma unroll
            for (int mb = 0; mb < 4; mb++)
#pragma unroll
                for (int nb = 0; nb < 4; nb++)
                    mma_bf16(acc[mb][nb], ah[mb], bl[nb]);   // hi*lo
#pragma unroll
            for (int mb = 0; mb < 4; mb++)
#pragma unroll
                for (int nb = 0; nb < 4; nb++)
                    mma_bf16(acc[mb][nb], al[mb], bh[nb]);   // lo*hi
        }
        if (it + 2 < 32) GEMM_ISSUE((it + 2) % 3, (it + 2) * 32);
    }

    // ---- Fused transposed epilogue: write T[b, c, l] (coalesced along l) ----
    float* sT = (float*)dsm;                 // 64 * 132 * 4 = 33792 B (fits)
    const int g = lane >> 2, t2 = (lane & 3) * 2;
    const int l0 = m0 & 2047;
    const int bq = m0 >> 11;

#pragma unroll
    for (int p = 0; p < 2; p++) {
        __syncthreads();
        if ((wn >> 1) == p) {
            const int chalf = (wn & 1) * 32;
#pragma unroll
            for (int mb = 0; mb < 4; mb++) {
                const int row = wm * 64 + mb * 16 + g;
#pragma unroll
                for (int nb = 0; nb < 4; nb++) {
                    const int cl = chalf + nb * 8 + t2;
                    const int cgl = n0 + p * 64 + cl;
                    const float b0 = bias[cgl], b1 = bias[cgl + 1];
                    sT[cl * 132 + row]           = acc[mb][nb][0] + b0;
                    sT[(cl + 1) * 132 + row]     = acc[mb][nb][1] + b1;
                    sT[cl * 132 + row + 8]       = acc[mb][nb][2] + b0;
                    sT[(cl + 1) * 132 + row + 8] = acc[mb][nb][3] + b1;
                }
            }
        }
        __syncthreads();
        const size_t cb = (size_t)bq * 1024 + n0 + p * 64;
#pragma unroll
        for (int i = tid; i < 2048; i += 256) {     // 64 c x 32 float4
            const int c = i >> 5, m4 = (i & 31) << 2;
            float4 v = *(float4*)&sT[c * 132 + m4];
            *(float4*)&T[((cb + c) << 11) + l0 + m4] = v;
        }
    }
}

// ---------------------------------------------------------------------------
// Small GEMM, coalesced: Y[64,1024] = X[64,1024] @ W + bias.
// Row r of X maps to X + (r/8)*b_stride + (r%8)*1024.
// ---------------------------------------------------------------------------
__global__ __launch_bounds__(256) void rowgemm64(
    const float* __restrict__ X, const float* __restrict__ W,
    const float* __restrict__ bias, float* __restrict__ Y, size_t b_stride)
{
    __shared__ float Xs[64][128];     // 32 KB
    __shared__ float Ws[16][129];

    const int tid = threadIdx.x;
    const int n0 = blockIdx.x * 16;
    const int n = tid & 15, rg = tid >> 4;   // 16 row-groups x 4 rows

    float a0 = 0.f, a1 = 0.f, a2 = 0.f, a3 = 0.f;

    for (int kt = 0; kt < 8; kt++) {
#pragma unroll
        for (int j = 0; j < 8; j++) {                 // X tile: 2048 float4
            const int i = tid + j * 256;
            const int row = i >> 5, c4 = (i & 31) << 2;
            const float* xr = X + (size_t)(row >> 3) * b_stride + (size_t)(row & 7) * 1024;
            *(float4*)&Xs[row][c4] = *(const float4*)(xr + kt * 128 + c4);
        }
#pragma unroll
        for (int j = 0; j < 8; j++) {                 // W tile: 128k x 16n -> Ws[n][k]
            const int i = tid + j * 256;
            const int k = i >> 4, nn = i & 15;
            Ws[nn][k] = W[(size_t)(kt * 128 + k) * 1024 + n0 + nn];
        }
        __syncthreads();
#pragma unroll 4
        for (int k = 0; k < 128; k++) {
            const float w = Ws[n][k];
            a0 += Xs[rg * 4 + 0][k] * w;
            a1 += Xs[rg * 4 + 1][k] * w;
            a2 += Xs[rg * 4 + 2][k] * w;
            a3 += Xs[rg * 4 + 3][k] * w;
        }
        __syncthreads();
    }
    const float bb = bias[n0 + n];
    Y[(size_t)(rg * 4 + 0) * 1024 + n0 + n] = a0 + bb;
    Y[(size_t)(rg * 4 + 1) * 1024 + n0 + n] = a1 + bb;
    Y[(size_t)(rg * 4 + 2) * 1024 + n0 + n] = a2 + bb;
    Y[(size_t)(rg * 4 + 3) * 1024 + n0 + n] = a3 + bb;
}

// ---------------------------------------------------------------------------
// Batched 2D transpose: out[b, j, i] = in[b, i, j], i<R, j<C (R,C mult of 32)
// ---------------------------------------------------------------------------
__global__ void transpose_bRC(const float* __restrict__ in, float* __restrict__ out,
                              int R, int C)
{
    __shared__ float tile[32][33];
    const int bz = blockIdx.z;
    const float* ip = in + (size_t)bz * R * C;
    float* op = out + (size_t)bz * R * C;
    const int j0 = blockIdx.x * 32;
    const int i0 = blockIdx.y * 32;
    const int tx = threadIdx.x, ty = threadIdx.y;
#pragma unroll
    for (int k = 0; k < 4; k++)
        tile[ty + k * 8][tx] = ip[(size_t)(i0 + ty + k * 8) * C + (j0 + tx)];
    __syncthreads();
#pragma unroll
    for (int k = 0; k < 4; k++)
        op[(size_t)(j0 + ty + k * 8) * R + (i0 + tx)] = tile[tx][ty + k * 8];
}

// ---------------------------------------------------------------------------
// FFT twiddle table: g_tw[e] = (cos, sin)(2 pi e / 2048), e < 1024
// ---------------------------------------------------------------------------
__global__ void fill_tw(float2* tw)
{
    const int i = blockIdx.x * 256 + threadIdx.x;
    if (i < 1024) {
        float s, c;
        sincosf(6.28318530717958647692f * (float)i / 2048.0f, &s, &c);
        tw[i] = make_float2(c, s);
    }
}

// ---------------------------------------------------------------------------
// Register-resident mixed-radix FFT pieces, N=2048 = 16 * 16 * 8, 128 threads.
// Stockham: y_m = DFT_R(x)_m * w2048^{m*p*s}, outputs at q + R*s*p + m*s.
// ---------------------------------------------------------------------------
#define PD(i) ((i) + ((i) >> 4))
#define FFT_SSZ 2176

__device__ __forceinline__ float2 cmul(float2 a, float2 b) {
    return make_float2(a.x * b.x - a.y * b.y, a.x * b.y + a.y * b.x);
}
__device__ __forceinline__ float2 twget(const float2* tw, int e, float sign) {
    float2 t = __ldg(&tw[e & 1023]);
    const float fl = (e & 1024) ? -1.0f : 1.0f;
    return make_float2(fl * t.x, fl * sign * t.y);
}
__device__ __forceinline__ void dft4(float2& x0, float2& x1, float2& x2, float2& x3,
                                     float sign) {
    const float apcx = x0.x + x2.x, apcy = x0.y + x2.y;
    const float amcx = x0.x - x2.x, amcy = x0.y - x2.y;
    const float bpdx = x1.x + x3.x, bpdy = x1.y + x3.y;
    const float bmdx = x1.x - x3.x, bmdy = x1.y - x3.y;
    x0 = make_float2(apcx + bpdx, apcy + bpdy);
    x1 = make_float2(amcx - sign * bmdy, amcy + sign * bmdx);
    x2 = make_float2(apcx - bpdx, apcy - bpdy);
    x3 = make_float2(amcx + sign * bmdy, amcy - sign * bmdx);
}
__device__ __forceinline__ void dft16(float2* x, const float2* tw, float sign) {
#pragma unroll
    for (int j1 = 0; j1 < 4; j1++)
        dft4(x[j1], x[j1 + 4], x[j1 + 8], x[j1 + 12], sign);
#pragma unroll
    for (int j1 = 1; j1 < 4; j1++)
#pragma unroll
        for (int k2 = 1; k2 < 4; k2++)
            x[j1 + 4 * k2] = cmul(x[j1 + 4 * k2], twget(tw, 128 * j1 * k2, sign));
#pragma unroll
    for (int k2 = 0; k2 < 4; k2++)
        dft4(x[4 * k2], x[1 + 4 * k2], x[2 + 4 * k2], x[3 + 4 * k2], sign);
}
__device__ __forceinline__ void dft8(float2* x, float sign) {
    const float s2 = 0.70710678118654752440f;
    float2 e[4], o[4];
#pragma unroll
    for (int j = 0; j < 4; j++) {
        e[j] = make_float2(x[j].x + x[j + 4].x, x[j].y + x[j + 4].y);
        o[j] = make_float2(x[j].x - x[j + 4].x, x[j].y - x[j + 4].y);
    }
    o[1] = cmul(o[1], make_float2(s2, sign * s2));
    o[2] = make_float2(-sign * o[2].y, sign * o[2].x);
    o[3] = cmul(o[3], make_float2(-s2, sign * s2));
    dft4(e[0], e[1], e[2], e[3], sign);
    dft4(o[0], o[1], o[2], o[3], sign);
#pragma unroll
    for (int k = 0; k < 4; k++) { x[2 * k] = e[k]; x[2 * k + 1] = o[k]; }
}

// Stage A (radix-16, s=1): x in regs -> Sout (with twiddle)
__device__ __forceinline__ void stageA(float2* x, float2* Sout, const float2* tw,
                                       int tid, float sign)
{
    dft16(x, tw, sign);
#pragma unroll
    for (int s = 0; s < 16; s++) {
        const int m = (s >> 2) | ((s & 3) << 2);
        Sout[PD(16 * tid + m)] = cmul(x[s], twget(tw, m * tid, sign));
    }
}
// Stage B (radix-16, s=16): Sin -> Sout (with twiddle)
__device__ __forceinline__ void stageB(float2* x, const float2* Sin, float2* Sout,
                                       const float2* tw, int tid, float sign)
{
    const int q = tid & 15, p = tid >> 4;
#pragma unroll
    for (int m = 0; m < 16; m++) x[m] = Sin[PD(q + 16 * p + 128 * m)];
    dft16(x, tw, sign);
    const int e = 16 * p;
    const int ob = q + 256 * p;
#pragma unroll
    for (int s = 0; s < 16; s++) {
        const int m = (s >> 2) | ((s & 3) << 2);
        Sout[PD(ob + 16 * m)] = cmul(x[s], twget(tw, m * e, sign));
    }
}

// ---------------------------------------------------------------------------
// Per-(b,c) kernel: fused FFT-correlation pipeline (5 barriers) -> corr +
// parallel top-22 (single barrier per round) + softmax + mod-8 V aggregation.
// ---------------------------------------------------------------------------
__global__ __launch_bounds__(128) void fft_corr_topk(
    const float* __restrict__ Qt, const float* __restrict__ Kt,
    const float* __restrict__ Vs, const float2* __restrict__ twg,
    float* __restrict__ corrS, float* __restrict__ Rsmall)
{
    __shared__ float2 S1[FFT_SSZ];
    __shared__ float2 S2[FFT_SSZ];
    __shared__ float topv[TOPK];
    __shared__ int   topd[TOPK];
    __shared__ float wts[TOPK];
    __shared__ float vsh[8];
    __shared__ float wv[2][4];
    __shared__ int   wi[2][4];

    const int tid = threadIdx.x;
    const int lane = tid & 31, warp = tid >> 5;
    const int bidx = blockIdx.x;              // b*1024 + c
    const int b = bidx >> 10;
    const int c = bidx & 1023;

    const float* qp = Qt + (size_t)bidx * 2048;
    const float* kp = Kt + (size_t)bidx * 2048;

    float2 x[16];
    // ---- forward FFT of z = q + i*k ----
#pragma unroll
    for (int m = 0; m < 16; m++) {
        const int n = tid + (m << 7);
        x[m] = make_float2(qp[n], kp[n]);
    }
    stageA(x, S1, twg, tid, -1.0f);
    __syncthreads();
    stageB(x, S1, S2, twg, tid, -1.0f);
    __syncthreads();
    // fwd stage C (radix-8, twiddle-free): S2 -> S1 natural order
#pragma unroll
    for (int h = 0; h < 2; h++) {
        const int q = tid + 128 * h;
        float2 y[8];
#pragma unroll
        for (int m = 0; m < 8; m++) y[m] = S2[PD(q + 256 * m)];
        dft8(y, -1.0f);
#pragma unroll
        for (int m = 0; m < 8; m++) S1[PD(q + 256 * m)] = y[m];
    }
    __syncthreads();

    // ---- pointwise P[f] = 0.25i*(a+conj(b))*(conj(a)-b) -> straight to regs
    // (f = tid + 128m is exactly the inverse stage-A input layout)
#pragma unroll
    for (int m = 0; m < 16; m++) {
        const int f = tid + (m << 7);
        float2 a  = S1[PD(f)];
        float2 bz = S1[PD((2048 - f) & 2047)];
        float ux = a.x + bz.x, uy = a.y - bz.y;
        float vx = a.x - bz.x, vy = -a.y - bz.y;
        float pr = ux * vx - uy * vy;
        float pi = ux * vy + uy * vx;
        x[m] = make_float2(-0.25f * pi, 0.25f * pr);
    }
    // ---- inverse FFT (stage A writes S2 — S1 still being read is safe) ----
    stageA(x, S2, twg, tid, +1.0f);
    __syncthreads();     // covers: pointwise S1 reads done; S2 stage-A complete
    stageB(x, S2, S1, twg, tid, +1.0f);
    __syncthreads();

    // ---- inverse stage C fused with corr output + top-k value capture ----
    // thread holds corr[n], n = q + 256m = tid + 128*(2m+h)  ->  vals[j], j=2m+h
    const float invN = 1.0f / 2048.0f;
    float* cg = corrS + (size_t)bidx * 2048;
    float vals[16];
#pragma unroll
    for (int h = 0; h < 2; h++) {
        const int q = tid + 128 * h;
        float2 y[8];
#pragma unroll
        for (int m = 0; m < 8; m++) y[m] = S1[PD(q + 256 * m)];
        dft8(y, +1.0f);
#pragma unroll
        for (int m = 0; m < 8; m++) {
            const float v = y[m].x * invN;
            vals[2 * m + h] = v;
            cg[q + 256 * m] = v;
        }
    }

    // local argmax over vals[j] with global index n = tid + 128j
    // (ascending j == ascending n => lowest-index tie-break preserved)
    float lmax = vals[0]; int lidx = tid;
#pragma unroll
    for (int j = 1; j < 16; j++) {
        const int ii = tid + (j << 7);
        if (vals[j] > lmax) { lmax = vals[j]; lidx = ii; }
    }

    // ---- top-22: one barrier per round; all threads redundantly pick winner --
    for (int r = 0; r < TOPK; r++) {
        const int pb = r & 1;
        float bvv = lmax; int bii = lidx;
#pragma unroll
        for (int off = 16; off > 0; off >>= 1) {
            const float ov = __shfl_down_sync(0xffffffffu, bvv, off);
            const int   oi = __shfl_down_sync(0xffffffffu, bii, off);
            if (ov > bvv || (ov == bvv && oi < bii)) { bvv = ov; bii = oi; }
        }
        if (lane == 0) { wv[pb][warp] = bvv; wi[pb][warp] = bii; }
        __syncthreads();
        float v2 = wv[pb][0]; int i2 = wi[pb][0];
#pragma unroll
        for (int w = 1; w < 4; w++) {
            const float ww = wv[pb][w]; const int qq = wi[pb][w];
            if (ww > v2 || (ww == v2 && qq < i2)) { v2 = ww; i2 = qq; }
        }
        if (tid == 0) { topv[r] = v2; topd[r] = i2; }
        if ((i2 & 127) == tid) {
            const int jj = i2 >> 7;
#pragma unroll
            for (int j = 0; j < 16; j++) if (j == jj) vals[j] = -1e30f;
            lmax = vals[0]; lidx = tid;
#pragma unroll
            for (int j = 1; j < 16; j++) {
                const int ii = tid + (j << 7);
                if (vals[j] > lmax) { lmax = vals[j]; lidx = ii; }
            }
        }
    }
    __syncthreads();   // topv/topd visible to warp 0

    // ---- softmax over top-22 + mod-8 aggregation (warp 0) ----
    if (tid < 32) {
        float e = 0.0f;
        const float mx = topv[0];
        if (lane < TOPK) { e = expf(topv[lane] - mx); wts[lane] = e; }
        float ssum = e;
#pragma unroll
        for (int off = 16; off > 0; off >>= 1)
            ssum += __shfl_down_sync(0xffffffffu, ssum, off);
        ssum = __shfl_sync(0xffffffffu, ssum, 0);
        const float inv = 1.0f / ssum;
        if (lane < 8) vsh[lane] = Vs[(size_t)(((b << 3) + lane) << 10) + c];
        __syncwarp();
        if (lane < 8) {
            float acc = 0.0f;
#pragma unroll
            for (int i = 0; i < TOPK; i++)
                acc += wts[i] * vsh[(lane + topd[i]) & 7];
            Rsmall[(size_t)(((b << 3) + lane) << 10) + c] = acc * inv;
        }
    }
}

// ---------------------------------------------------------------------------
// Broadcast: out[b,l,:] = Tout[b*8 + (l%8), :]
// ---------------------------------------------------------------------------
__global__ void broadcast_out(const float* __restrict__ Tout, float* __restrict__ out)
{
    const size_t idx = (size_t)blockIdx.x * 256 + threadIdx.x;  // < ELEMS
    const int cc = (int)(idx & 1023);
    const int l  = (int)((idx >> 10) & 2047);
    const int bb = (int)(idx >> 21);
    out[idx] = Tout[(size_t)(((bb << 3) + (l & 7)) << 10) + cc];
}

// ---------------------------------------------------------------------------
extern "C" void kernel_launch(void* const* d_in, const int* in_sizes, int n_in,
                              void* d_out, int out_size)
{
    (void)in_sizes; (void)n_in; (void)out_size;
    const float* queries = (const float*)d_in[0];
    const float* keys    = (const float*)d_in[1];
    const float* values  = (const float*)d_in[2];
    const float* Wq = (const float*)d_in[3];
    const float* bq = (const float*)d_in[4];
    const float* Wk = (const float*)d_in[5];
    const float* bk = (const float*)d_in[6];
    const float* Wv = (const float*)d_in[7];
    const float* bv = (const float*)d_in[8];
    const float* Wo = (const float*)d_in[9];
    const float* bo = (const float*)d_in[10];
    float* out = (float*)d_out;

    float *Qt, *Kt, *corrS, *Vs, *Rs, *To;
    __nv_bfloat16 *Xhi, *Xlo, *Whi, *Wlo;
    float2* twp;
    cudaGetSymbolAddress((void**)&Qt, g_Qt);
    cudaGetSymbolAddress((void**)&Kt, g_Kt);
    cudaGetSymbolAddress((void**)&corrS, g_corr);
    cudaGetSymbolAddress((void**)&Vs, g_Vs);
    cudaGetSymbolAddress((void**)&Rs, g_Rs);
    cudaGetSymbolAddress((void**)&To, g_To);
    cudaGetSymbolAddress((void**)&Xhi, g_Xhi);
    cudaGetSymbolAddress((void**)&Xlo, g_Xlo);
    cudaGetSymbolAddress((void**)&Whi, g_Whi);
    cudaGetSymbolAddress((void**)&Wlo, g_Wlo);
    cudaGetSymbolAddress((void**)&twp, g_tw);

    static int attr_done = 0;
    if (!attr_done) {
        cudaFuncSetAttribute(gemm_bf16x2_t,
                             cudaFuncAttributeMaxDynamicSharedMemorySize, GEMM_DSMEM);
        attr_done = 1;
    }

    fill_tw<<<4, 256>>>(twp);

    dim3 gemmGrid(1024 / 128, (BATCH * SEQ) / 128);  // (8, 128)

    // Q projection on tensor cores (split-bf16, 3 products), writes Qt directly
    split_bf16<<<ELEMS / 1024, 256>>>(queries, Xhi, Xlo);
    split_bf16<<<(DIM * DIM) / 1024, 256>>>(Wq, Whi, Wlo);
    gemm_bf16x2_t<<<gemmGrid, 256, GEMM_DSMEM>>>(Xhi, Xlo, Whi, Wlo, bq, Qt);

    // K projection, writes Kt directly
    split_bf16<<<ELEMS / 1024, 256>>>(keys, Xhi, Xlo);
    split_bf16<<<(DIM * DIM) / 1024, 256>>>(Wk, Whi, Wlo);
    gemm_bf16x2_t<<<gemmGrid, 256, GEMM_DSMEM>>>(Xhi, Xlo, Whi, Wlo, bk, Kt);

    // V projection: only rows l = 0..7 per batch matter (mod-8 quirk)
    rowgemm64<<<64, 256>>>(values, Wv, bv, Vs, (size_t)SEQ * DIM);

    // FFT correlation + top-k + mod-8 aggregation
    fft_corr_topk<<<BATCH * DIM, 128>>>(Qt, Kt, Vs, twp, corrS, Rs);

    // corr [B,C,L] -> second output half [B,L,C]
    transpose_bRC<<<dim3(2048 / 32, 1024 / 32, BATCH), dim3(32, 8)>>>(corrS, out + (size_t)ELEMS, 1024, 2048);

    // out = result @ Wo + bo  (result rows periodic: 64 distinct rows)
    rowgemm64<<<64, 256>>>(Rs, Wo, bo, To, (size_t)8 * DIM);
    broadcast_out<<<ELEMS / 256, 256>>>(To, out);
}